// round 6
// baseline (speedup 1.0000x reference)
#include <cuda_runtime.h>
#include <cuda_bf16.h>
#include <cuda_fp16.h>
#include <cstdint>

// Problem constants
#define BN 32768
#define DN 256
#define KN 2048

// Output layout (fp32, concatenated in reference return order)
#define Q_OFF    0
#define TAIL_OFF (BN*DN)
#define IND_OFF  (BN*DN + 2)

// Stage-2 shortlist margin (worst-case bf16 path error ~1.3e-3; 3x safety)
#define MARGIN 4.0e-3f

// Scratch (device globals; no allocation allowed)
__device__ float g_rowA[BN];            // sum(latents^2) per row
__device__ float g_rowB[KN];            // sum(embedding^2) per code
__device__ float g_minval[BN];          // exact min dist per row
__device__ int   g_minidx[BN];          // exact argmin index per row
__device__ int   g_counts[KN];          // histogram
__device__ float g_sqsum;               // sum (q - l)^2
__device__ float g_mindsum;             // sum of min dists
__device__ __nv_bfloat16 g_latbf[(size_t)BN * DN];  // bf16 latents
__device__ __nv_bfloat16 g_embbf[(size_t)KN * DN];  // bf16 embedding
__device__ __half        g_s[(size_t)BN * KN];      // approx s = B_k - 2*dot (fp16)

// ---------------------------------------------------------------------------
__global__ void vq_init()
{
    int t = blockIdx.x * blockDim.x + threadIdx.x;
    if (t < KN) g_counts[t] = 0;
    if (t == 0) { g_sqsum = 0.f; g_mindsum = 0.f; }
}

// Row sum of squares (reference-shadowing rounding), fused bf16 conversion.
__global__ void vq_rowsumsq(const float* __restrict__ x, int nrows, int which)
{
    int gw   = (blockIdx.x * blockDim.x + threadIdx.x) >> 5;
    int lane = threadIdx.x & 31;
    if (gw >= nrows) return;
    const float* row = x + (size_t)gw * DN;
    float s = 0.f;
    #pragma unroll
    for (int j = 0; j < DN / 32; j++) {
        float v = row[lane + 32 * j];
        s = __fadd_rn(s, __fmul_rn(v, v));
        __nv_bfloat16 bv = __float2bfloat16(v);   // rne
        if (which) g_embbf[(size_t)gw * DN + lane + 32 * j] = bv;
        else       g_latbf[(size_t)gw * DN + lane + 32 * j] = bv;
    }
    #pragma unroll
    for (int off = 16; off > 0; off >>= 1)
        s = __fadd_rn(s, __shfl_down_sync(0xffffffffu, s, off));
    if (lane == 0) {
        if (which) g_rowB[gw] = s; else g_rowA[gw] = s;
    }
}

// ---------------------------------------------------------------------------
// Stage 1: bf16 warp-MMA GEMM (mma.sync m16n8k16 — baseline PTX, no 'a' gate).
// Block = 128 rows x 128 codes x K=256 (whole K resident in smem).
// 8 warps in 2(m) x 4(n); warp tile = 64 x 32.
// Emits s = B_k - 2*dot (fp16) for every (row, code) pair.
//
// Smem layout: row-major 512B rows (256 bf16), 16B chunks XOR-swizzled:
//   chunk_stored = chunk ^ (row & 7)  -> conflict-free ldmatrix & stores.
// ---------------------------------------------------------------------------
#define A_OFF  0
#define B_OFF  65536
#define B2_OFF 131072
#define SMEM_TOT (131072 + 512)

__device__ __forceinline__ void ldsm_x4(uint32_t& r0, uint32_t& r1,
                                        uint32_t& r2, uint32_t& r3, uint32_t addr)
{
    asm volatile("ldmatrix.sync.aligned.m8n8.x4.shared.b16 {%0,%1,%2,%3}, [%4];"
                 : "=r"(r0), "=r"(r1), "=r"(r2), "=r"(r3) : "r"(addr));
}
__device__ __forceinline__ void ldsm_x2(uint32_t& r0, uint32_t& r1, uint32_t addr)
{
    asm volatile("ldmatrix.sync.aligned.m8n8.x2.shared.b16 {%0,%1}, [%2];"
                 : "=r"(r0), "=r"(r1) : "r"(addr));
}
__device__ __forceinline__ void mma_bf16(float* c, uint32_t a0, uint32_t a1,
                                         uint32_t a2, uint32_t a3,
                                         uint32_t b0, uint32_t b1)
{
    asm volatile(
        "mma.sync.aligned.m16n8k16.row.col.f32.bf16.bf16.f32 "
        "{%0,%1,%2,%3}, {%4,%5,%6,%7}, {%8,%9}, {%0,%1,%2,%3};"
        : "+f"(c[0]), "+f"(c[1]), "+f"(c[2]), "+f"(c[3])
        : "r"(a0), "r"(a1), "r"(a2), "r"(a3), "r"(b0), "r"(b1));
}
__device__ __forceinline__ uint32_t smem_u32(const void* p) {
    uint32_t a;
    asm("{ .reg .u64 t; cvta.to.shared.u64 t, %1; cvt.u32.u64 %0, t; }"
        : "=r"(a) : "l"(p));
    return a;
}

__global__ __launch_bounds__(256, 1) void vq_gemm()
{
    extern __shared__ char smem[];
    uint32_t smem_base = smem_u32(smem);
    float* b2s = (float*)(smem + B2_OFF);

    int tid  = threadIdx.x;
    int wid  = tid >> 5;
    int lane = tid & 31;
    int gid  = lane >> 2;       // mma group id (row within 8)
    int tig  = lane & 3;        // thread-in-group (col pair)
    int wm   = wid >> 2;        // 0..1
    int wn   = wid & 3;         // 0..3

    int row0 = (blockIdx.x >> 4) * 128;
    int kc0  = (blockIdx.x & 15) * 128;

    // Load A tile: rows row0..+127, 256 bf16 each (512B), swizzled chunks
    for (int i = tid; i < 4096; i += 256) {
        int r = i >> 5;
        int c = i & 31;
        uint4 v = *reinterpret_cast<const uint4*>(g_latbf + (size_t)(row0 + r) * DN + c * 8);
        *reinterpret_cast<uint4*>(smem + A_OFF + r * 512 + ((c ^ (r & 7)) << 4)) = v;
    }
    // Load B tile: codes kc0..+127
    for (int i = tid; i < 4096; i += 256) {
        int r = i >> 5;
        int c = i & 31;
        uint4 v = *reinterpret_cast<const uint4*>(g_embbf + (size_t)(kc0 + r) * DN + c * 8);
        *reinterpret_cast<uint4*>(smem + B_OFF + r * 512 + ((c ^ (r & 7)) << 4)) = v;
    }
    if (tid < 128) b2s[tid] = g_rowB[kc0 + tid];
    __syncthreads();

    float acc[4][4][4];
    #pragma unroll
    for (int mt = 0; mt < 4; mt++)
        #pragma unroll
        for (int nt = 0; nt < 4; nt++)
            #pragma unroll
            for (int q = 0; q < 4; q++) acc[mt][nt][q] = 0.f;

    int j  = lane >> 3;         // ldmatrix address group 0..3
    int rin = lane & 7;

    #pragma unroll 4
    for (int kt = 0; kt < 16; kt++) {
        // A fragments: 4 m-tiles
        uint32_t af[4][4];
        #pragma unroll
        for (int mt = 0; mt < 4; mt++) {
            int row = wm * 64 + mt * 16 + (j & 1) * 8 + rin;
            int ch  = 2 * kt + (j >> 1);
            uint32_t addr = smem_base + A_OFF + row * 512 + ((ch ^ (row & 7)) << 4);
            ldsm_x4(af[mt][0], af[mt][1], af[mt][2], af[mt][3], addr);
        }
        // B fragments: 4 n-tiles (x2 uses address groups 0,1)
        uint32_t bf[4][2];
        #pragma unroll
        for (int nt = 0; nt < 4; nt++) {
            int code = wn * 32 + nt * 8 + rin;
            int ch   = 2 * kt + (j & 1);
            uint32_t addr = smem_base + B_OFF + code * 512 + ((ch ^ (code & 7)) << 4);
            ldsm_x2(bf[nt][0], bf[nt][1], addr);
        }
        #pragma unroll
        for (int mt = 0; mt < 4; mt++)
            #pragma unroll
            for (int nt = 0; nt < 4; nt++)
                mma_bf16(acc[mt][nt], af[mt][0], af[mt][1], af[mt][2], af[mt][3],
                         bf[nt][0], bf[nt][1]);
    }

    // Epilogue: s = B2[code] - 2*acc, store fp16
    #pragma unroll
    for (int mt = 0; mt < 4; mt++) {
        int r0 = wm * 64 + mt * 16 + gid;
        #pragma unroll
        for (int nt = 0; nt < 4; nt++) {
            int c0 = wn * 32 + nt * 8 + tig * 2;
            float b20 = b2s[c0], b21 = b2s[c0 + 1];
            float s00 = b20 - 2.0f * acc[mt][nt][0];
            float s01 = b21 - 2.0f * acc[mt][nt][1];
            float s10 = b20 - 2.0f * acc[mt][nt][2];
            float s11 = b21 - 2.0f * acc[mt][nt][3];
            *reinterpret_cast<__half2*>(g_s + (size_t)(row0 + r0) * KN + kc0 + c0)
                = __floats2half2_rn(s00, s01);
            *reinterpret_cast<__half2*>(g_s + (size_t)(row0 + r0 + 8) * KN + kc0 + c0)
                = __floats2half2_rn(s10, s11);
        }
    }
}

// ---------------------------------------------------------------------------
// Stage 2: exact re-check. One warp per row. Row's 2048 fp16 s values live in
// registers; compute row min, then candidates within MARGIN are recomputed
// with the bit-exact reference rounding; argmin w/ lowest-index tie-break.
// ---------------------------------------------------------------------------
__global__ __launch_bounds__(256) void vq_select(const float* __restrict__ lat,
                                                 const float* __restrict__ emb)
{
    int gw   = (blockIdx.x * blockDim.x + threadIdx.x) >> 5;
    int lane = threadIdx.x & 31;
    if (gw >= BN) return;

    const __half* srow = g_s + (size_t)gw * KN;

    // lane owns codes [lane*64, lane*64+64): 32 half2 regs
    uint32_t sv[32];
    #pragma unroll
    for (int q = 0; q < 8; q++) {
        uint4 v = *reinterpret_cast<const uint4*>(srow + lane * 64 + q * 8);
        sv[q * 4 + 0] = v.x; sv[q * 4 + 1] = v.y;
        sv[q * 4 + 2] = v.z; sv[q * 4 + 3] = v.w;
    }
    // lane-local min (half2 tree), then warp min
    __half2 m2 = *reinterpret_cast<const __half2*>(&sv[0]);
    #pragma unroll
    for (int q = 1; q < 32; q++)
        m2 = __hmin2(m2, *reinterpret_cast<const __half2*>(&sv[q]));
    float mn = fminf(__low2float(m2), __high2float(m2));
    #pragma unroll
    for (int off = 16; off > 0; off >>= 1)
        mn = fminf(mn, __shfl_xor_sync(0xffffffffu, mn, off));
    float thr = mn + MARGIN;

    float A = g_rowA[gw];
    const float4* lrow = reinterpret_cast<const float4*>(lat + (size_t)gw * DN);

    float bestd = __int_as_float(0x7f800000);
    int   bestk = 0x7fffffff;

    #pragma unroll
    for (int q = 0; q < 32; q++) {
        __half2 h = *reinterpret_cast<const __half2*>(&sv[q]);
        float f0 = __low2float(h), f1 = __high2float(h);
        #pragma unroll
        for (int e = 0; e < 2; e++) {
            float f = e ? f1 : f0;
            if (f <= thr) {
                int k = lane * 64 + q * 2 + e;
                const float4* erow = reinterpret_cast<const float4*>(emb + (size_t)k * DN);
                float acc = 0.f;
                for (int t = 0; t < 64; t++) {
                    float4 a = lrow[t], b = erow[t];
                    acc = __fmaf_rn(a.x, b.x, acc);
                    acc = __fmaf_rn(a.y, b.y, acc);
                    acc = __fmaf_rn(a.z, b.z, acc);
                    acc = __fmaf_rn(a.w, b.w, acc);
                }
                float d = __fsub_rn(__fadd_rn(A, g_rowB[k]), __fmul_rn(2.0f, acc));
                if (d < bestd || (d == bestd && k < bestk)) { bestd = d; bestk = k; }
            }
        }
    }
    #pragma unroll
    for (int off = 16; off > 0; off >>= 1) {
        float ov = __shfl_down_sync(0xffffffffu, bestd, off);
        int   oi = __shfl_down_sync(0xffffffffu, bestk, off);
        if (ov < bestd || (ov == bestd && oi < bestk)) { bestd = ov; bestk = oi; }
    }
    if (lane == 0) { g_minval[gw] = bestd; g_minidx[gw] = bestk; }
}

// ---------------------------------------------------------------------------
__global__ void vq_hist(float* __restrict__ out_inds)
{
    __shared__ float s[256];
    int b = blockIdx.x * blockDim.x + threadIdx.x;
    float v = 0.f;
    if (b < BN) {
        int idx = g_minidx[b];
        out_inds[b] = (float)idx;
        atomicAdd(&g_counts[idx], 1);
        v = g_minval[b];
    }
    s[threadIdx.x] = v;
    __syncthreads();
    for (int o = 128; o > 0; o >>= 1) {
        if (threadIdx.x < o) s[threadIdx.x] += s[threadIdx.x + o];
        __syncthreads();
    }
    if (threadIdx.x == 0) atomicAdd(&g_mindsum, s[0]);
}

__global__ void vq_gather(const float* __restrict__ lat, const float* __restrict__ emb,
                          float* __restrict__ outq)
{
    __shared__ float s[256];
    int i4 = blockIdx.x * blockDim.x + threadIdx.x;
    float ls = 0.f;
    if (i4 < BN * DN / 4) {
        int b   = i4 >> 6;
        int idx = g_minidx[b];
        float4 l = reinterpret_cast<const float4*>(lat)[i4];
        float4 q = reinterpret_cast<const float4*>(emb)[(size_t)idx * (DN / 4) + (i4 & 63)];
        float4 o; float d;
        d = __fsub_rn(q.x, l.x); o.x = __fadd_rn(l.x, d); ls = __fmaf_rn(d, d, ls);
        d = __fsub_rn(q.y, l.y); o.y = __fadd_rn(l.y, d); ls = __fmaf_rn(d, d, ls);
        d = __fsub_rn(q.z, l.z); o.z = __fadd_rn(l.z, d); ls = __fmaf_rn(d, d, ls);
        d = __fsub_rn(q.w, l.w); o.w = __fadd_rn(l.w, d); ls = __fmaf_rn(d, d, ls);
        reinterpret_cast<float4*>(outq)[i4] = o;
    }
    s[threadIdx.x] = ls;
    __syncthreads();
    for (int o2 = 128; o2 > 0; o2 >>= 1) {
        if (threadIdx.x < o2) s[threadIdx.x] += s[threadIdx.x + o2];
        __syncthreads();
    }
    if (threadIdx.x == 0) atomicAdd(&g_sqsum, s[0]);
}

__global__ void vq_finalize(float* __restrict__ out_tail)
{
    __shared__ float s[256];
    float loc = 0.f;
    for (int k = threadIdx.x; k < KN; k += 256) {
        float p = (float)g_counts[k] * (1.0f / BN);
        loc += p * logf(p + 1e-10f);
    }
    s[threadIdx.x] = loc;
    __syncthreads();
    for (int o = 128; o > 0; o >>= 1) {
        if (threadIdx.x < o) s[threadIdx.x] += s[threadIdx.x + o];
        __syncthreads();
    }
    if (threadIdx.x == 0) {
        float mse = g_sqsum * (1.0f / (float)(BN * (size_t)DN));
        out_tail[0] = __fadd_rn(__fmul_rn(mse, 0.25f), mse);
        out_tail[1] = -s[0];
        out_tail[2 + BN] = g_mindsum * (1.0f / BN);
    }
}

// ---------------------------------------------------------------------------
extern "C" void kernel_launch(void* const* d_in, const int* in_sizes, int n_in,
                              void* d_out, int out_size)
{
    (void)in_sizes; (void)n_in; (void)out_size;
    const float* lat = (const float*)d_in[0];   // [BN, DN] fp32
    const float* emb = (const float*)d_in[1];   // [KN, DN] fp32
    float* out = (float*)d_out;

    cudaFuncSetAttribute(vq_gemm,
                         cudaFuncAttributeMaxDynamicSharedMemorySize, SMEM_TOT);

    vq_init<<<(KN + 255) / 256, 256>>>();
    vq_rowsumsq<<<(BN * 32) / 256, 256>>>(lat, BN, 0);
    vq_rowsumsq<<<(KN * 32) / 256, 256>>>(emb, KN, 1);
    vq_gemm<<<(BN / 128) * (KN / 128), 256, SMEM_TOT>>>();
    vq_select<<<BN / 8, 256>>>(lat, emb);
    vq_hist<<<BN / 256, 256>>>(out + IND_OFF);
    vq_gather<<<(BN * DN / 4) / 256, 256>>>(lat, emb, out + Q_OFF);
    vq_finalize<<<1, 256>>>(out + TAIL_OFF);
}

// round 7
// speedup vs baseline: 8.0487x; 8.0487x over previous
#include <cuda_runtime.h>
#include <cuda_bf16.h>
#include <cuda_fp16.h>
#include <cstdint>

// Problem constants
#define BN 32768
#define DN 256
#define KN 2048

// Output layout (fp32, concatenated in reference return order)
#define Q_OFF    0
#define TAIL_OFF (BN*DN)
#define IND_OFF  (BN*DN + 2)

// Stage-2 shortlist margin (worst-case bf16 path error ~1.4e-3; need >= 2x)
#define MARGIN 4.0e-3f

// Scratch (device globals; no allocation allowed)
__device__ float g_rowA[BN];            // sum(latents^2) per row
__device__ float g_rowB[KN];            // sum(embedding^2) per code
__device__ float g_minval[BN];          // exact min dist per row
__device__ int   g_minidx[BN];          // exact argmin index per row
__device__ int   g_counts[KN];          // histogram
__device__ float g_sqsum;               // sum (q - l)^2
__device__ float g_mindsum;             // sum of min dists
__device__ __nv_bfloat16 g_latbf[(size_t)BN * DN];  // bf16 latents
__device__ __nv_bfloat16 g_embbf[(size_t)KN * DN];  // bf16 embedding
__device__ __half        g_s[(size_t)BN * KN];      // approx s = B_k - 2*dot (fp16)

// ---------------------------------------------------------------------------
__global__ void vq_init()
{
    int t = blockIdx.x * blockDim.x + threadIdx.x;
    if (t < KN) g_counts[t] = 0;
    if (t == 0) { g_sqsum = 0.f; g_mindsum = 0.f; }
}

// Row sum of squares (reference-shadowing rounding), fused bf16 conversion.
__global__ void vq_rowsumsq(const float* __restrict__ x, int nrows, int which)
{
    int gw   = (blockIdx.x * blockDim.x + threadIdx.x) >> 5;
    int lane = threadIdx.x & 31;
    if (gw >= nrows) return;
    const float* row = x + (size_t)gw * DN;
    float s = 0.f;
    #pragma unroll
    for (int j = 0; j < DN / 32; j++) {
        float v = row[lane + 32 * j];
        s = __fadd_rn(s, __fmul_rn(v, v));
        __nv_bfloat16 bv = __float2bfloat16(v);   // rne
        if (which) g_embbf[(size_t)gw * DN + lane + 32 * j] = bv;
        else       g_latbf[(size_t)gw * DN + lane + 32 * j] = bv;
    }
    #pragma unroll
    for (int off = 16; off > 0; off >>= 1)
        s = __fadd_rn(s, __shfl_down_sync(0xffffffffu, s, off));
    if (lane == 0) {
        if (which) g_rowB[gw] = s; else g_rowA[gw] = s;
    }
}

// ---------------------------------------------------------------------------
// Stage 1: bf16 warp-MMA GEMM (mma.sync m16n8k16).
// Block = 128 rows x 128 codes; K=256 processed as 2 chunks of 128 so smem is
// 64.5 KB -> 2 blocks/SM (load/compute overlap across blocks).
// 8 warps in 2(m) x 4(n); warp tile = 64 x 32.
// Emits s = B_k - 2*dot (fp16) for every (row, code) pair.
// Smem: row-major 256B rows (128 bf16), 16B chunks XOR-swizzled (c ^ (r&7)).
// ---------------------------------------------------------------------------
#define A_OFF  0
#define B_OFF  32768
#define B2_OFF 65536
#define SMEM_TOT (65536 + 512)

__device__ __forceinline__ void ldsm_x4(uint32_t& r0, uint32_t& r1,
                                        uint32_t& r2, uint32_t& r3, uint32_t addr)
{
    asm volatile("ldmatrix.sync.aligned.m8n8.x4.shared.b16 {%0,%1,%2,%3}, [%4];"
                 : "=r"(r0), "=r"(r1), "=r"(r2), "=r"(r3) : "r"(addr));
}
__device__ __forceinline__ void ldsm_x2(uint32_t& r0, uint32_t& r1, uint32_t addr)
{
    asm volatile("ldmatrix.sync.aligned.m8n8.x2.shared.b16 {%0,%1}, [%2];"
                 : "=r"(r0), "=r"(r1) : "r"(addr));
}
__device__ __forceinline__ void mma_bf16(float* c, uint32_t a0, uint32_t a1,
                                         uint32_t a2, uint32_t a3,
                                         uint32_t b0, uint32_t b1)
{
    asm volatile(
        "mma.sync.aligned.m16n8k16.row.col.f32.bf16.bf16.f32 "
        "{%0,%1,%2,%3}, {%4,%5,%6,%7}, {%8,%9}, {%0,%1,%2,%3};"
        : "+f"(c[0]), "+f"(c[1]), "+f"(c[2]), "+f"(c[3])
        : "r"(a0), "r"(a1), "r"(a2), "r"(a3), "r"(b0), "r"(b1));
}
__device__ __forceinline__ uint32_t smem_u32(const void* p) {
    uint32_t a;
    asm("{ .reg .u64 t; cvta.to.shared.u64 t, %1; cvt.u32.u64 %0, t; }"
        : "=r"(a) : "l"(p));
    return a;
}

__global__ __launch_bounds__(256, 2) void vq_gemm()
{
    extern __shared__ char smem[];
    uint32_t smem_base = smem_u32(smem);
    float* b2s = (float*)(smem + B2_OFF);

    int tid  = threadIdx.x;
    int wid  = tid >> 5;
    int lane = tid & 31;
    int gid  = lane >> 2;       // mma group id (row within 8)
    int tig  = lane & 3;        // thread-in-group (col pair)
    int wm   = wid >> 2;        // 0..1
    int wn   = wid & 3;         // 0..3

    int row0 = (blockIdx.x >> 4) * 128;
    int kc0  = (blockIdx.x & 15) * 128;

    if (tid < 128) b2s[tid] = g_rowB[kc0 + tid];

    float acc[4][4][4];
    #pragma unroll
    for (int mt = 0; mt < 4; mt++)
        #pragma unroll
        for (int nt = 0; nt < 4; nt++)
            #pragma unroll
            for (int q = 0; q < 4; q++) acc[mt][nt][q] = 0.f;

    int j   = lane >> 3;        // ldmatrix address group 0..3
    int rin = lane & 7;

    for (int kch = 0; kch < 2; kch++) {
        __syncthreads();        // previous chunk consumed before overwrite
        // Load A chunk: 128 rows x 128 bf16 (256B/row), 16B chunks swizzled
        for (int i = tid; i < 2048; i += 256) {
            int r = i >> 4;
            int c = i & 15;
            uint4 v = *reinterpret_cast<const uint4*>(
                g_latbf + (size_t)(row0 + r) * DN + kch * 128 + c * 8);
            *reinterpret_cast<uint4*>(smem + A_OFF + r * 256 + ((c ^ (r & 7)) << 4)) = v;
        }
        // Load B chunk
        for (int i = tid; i < 2048; i += 256) {
            int r = i >> 4;
            int c = i & 15;
            uint4 v = *reinterpret_cast<const uint4*>(
                g_embbf + (size_t)(kc0 + r) * DN + kch * 128 + c * 8);
            *reinterpret_cast<uint4*>(smem + B_OFF + r * 256 + ((c ^ (r & 7)) << 4)) = v;
        }
        __syncthreads();

        #pragma unroll
        for (int kt = 0; kt < 8; kt++) {
            uint32_t af[4][4];
            #pragma unroll
            for (int mt = 0; mt < 4; mt++) {
                int row = wm * 64 + mt * 16 + (j & 1) * 8 + rin;
                int ch  = 2 * kt + (j >> 1);
                uint32_t addr = smem_base + A_OFF + row * 256 + ((ch ^ (row & 7)) << 4);
                ldsm_x4(af[mt][0], af[mt][1], af[mt][2], af[mt][3], addr);
            }
            uint32_t bf[4][2];
            #pragma unroll
            for (int nt = 0; nt < 4; nt++) {
                int code = wn * 32 + nt * 8 + rin;
                int ch   = 2 * kt + (j & 1);
                uint32_t addr = smem_base + B_OFF + code * 256 + ((ch ^ (code & 7)) << 4);
                ldsm_x2(bf[nt][0], bf[nt][1], addr);
            }
            #pragma unroll
            for (int mt = 0; mt < 4; mt++)
                #pragma unroll
                for (int nt = 0; nt < 4; nt++)
                    mma_bf16(acc[mt][nt], af[mt][0], af[mt][1], af[mt][2], af[mt][3],
                             bf[nt][0], bf[nt][1]);
        }
    }

    // Epilogue: s = B2[code] - 2*acc, store fp16
    #pragma unroll
    for (int mt = 0; mt < 4; mt++) {
        int r0 = wm * 64 + mt * 16 + gid;
        #pragma unroll
        for (int nt = 0; nt < 4; nt++) {
            int c0 = wn * 32 + nt * 8 + tig * 2;
            float b20 = b2s[c0], b21 = b2s[c0 + 1];
            float s00 = b20 - 2.0f * acc[mt][nt][0];
            float s01 = b21 - 2.0f * acc[mt][nt][1];
            float s10 = b20 - 2.0f * acc[mt][nt][2];
            float s11 = b21 - 2.0f * acc[mt][nt][3];
            *reinterpret_cast<__half2*>(g_s + (size_t)(row0 + r0) * KN + kc0 + c0)
                = __floats2half2_rn(s00, s01);
            *reinterpret_cast<__half2*>(g_s + (size_t)(row0 + r0 + 8) * KN + kc0 + c0)
                = __floats2half2_rn(s10, s11);
        }
    }
}

// ---------------------------------------------------------------------------
// Stage 2: exact re-check, restructured.
// One warp per row; row's 2048 fp16 s staged in smem (4KB/warp, 32KB/block).
// Pass 1: streaming min. Pass 2: ballot-compacted candidates; each candidate's
// exact fp32 dot computed warp-cooperatively (8-deep fma/lane + shfl-xor tree).
// Argmin w/ lowest-index tie-break.
// ---------------------------------------------------------------------------
__global__ __launch_bounds__(256) void vq_select(const float* __restrict__ lat,
                                                 const float* __restrict__ emb)
{
    __shared__ __half srow_s[8][KN];    // 32 KB

    int wip  = threadIdx.x >> 5;        // warp in block
    int lane = threadIdx.x & 31;
    int gw   = blockIdx.x * 8 + wip;    // row
    if (gw >= BN) return;

    // Stage row into smem (coalesced uint4)
    const __half* srow = g_s + (size_t)gw * KN;
    #pragma unroll
    for (int q = 0; q < 8; q++) {
        *reinterpret_cast<uint4*>(&srow_s[wip][q * 256 + lane * 8]) =
            *reinterpret_cast<const uint4*>(srow + q * 256 + lane * 8);
    }
    __syncwarp();

    // Preload this row's latents (lane-strided) + A
    float lrow[8];
    #pragma unroll
    for (int u = 0; u < 8; u++) lrow[u] = lat[(size_t)gw * DN + lane + 32 * u];
    float A = g_rowA[gw];

    // Pass 1: min of s (fp16 pair tree, conflict-free half2 reads)
    const __half2* s2 = reinterpret_cast<const __half2*>(srow_s[wip]);
    __half2 m2 = s2[lane];
    #pragma unroll
    for (int c = 1; c < 32; c++) m2 = __hmin2(m2, s2[c * 32 + lane]);
    float mn = fminf(__low2float(m2), __high2float(m2));
    #pragma unroll
    for (int off = 16; off > 0; off >>= 1)
        mn = fminf(mn, __shfl_xor_sync(0xffffffffu, mn, off));
    float thr = mn + MARGIN;

    // Pass 2: candidates via ballot; cooperative exact recheck
    float bestd = __int_as_float(0x7f800000);
    int   bestk = 0x7fffffff;

    for (int c = 0; c < 32; c++) {
        __half2 h = s2[c * 32 + lane];
        float f0 = __low2float(h), f1 = __high2float(h);
        unsigned mask = __ballot_sync(0xffffffffu, (f0 <= thr) || (f1 <= thr));
        while (mask) {
            int src = __ffs(mask) - 1;
            mask &= mask - 1;
            __half2 hb = s2[c * 32 + src];     // broadcast read
            float fb0 = __low2float(hb), fb1 = __high2float(hb);
            #pragma unroll
            for (int e = 0; e < 2; e++) {
                float fb = e ? fb1 : fb0;
                if (fb <= thr) {
                    int k = (c * 32 + src) * 2 + e;
                    const float* erow = emb + (size_t)k * DN;
                    float acc = 0.f;
                    #pragma unroll
                    for (int u = 0; u < 8; u++)
                        acc = __fmaf_rn(lrow[u], erow[lane + 32 * u], acc);
                    #pragma unroll
                    for (int off = 16; off > 0; off >>= 1)
                        acc = __fadd_rn(acc, __shfl_xor_sync(0xffffffffu, acc, off));
                    float d = __fsub_rn(__fadd_rn(A, g_rowB[k]), __fmul_rn(2.0f, acc));
                    if (d < bestd || (d == bestd && k < bestk)) { bestd = d; bestk = k; }
                }
            }
        }
    }
    if (lane == 0) { g_minval[gw] = bestd; g_minidx[gw] = bestk; }
}

// ---------------------------------------------------------------------------
__global__ void vq_hist(float* __restrict__ out_inds)
{
    __shared__ float s[256];
    int b = blockIdx.x * blockDim.x + threadIdx.x;
    float v = 0.f;
    if (b < BN) {
        int idx = g_minidx[b];
        out_inds[b] = (float)idx;
        atomicAdd(&g_counts[idx], 1);
        v = g_minval[b];
    }
    s[threadIdx.x] = v;
    __syncthreads();
    for (int o = 128; o > 0; o >>= 1) {
        if (threadIdx.x < o) s[threadIdx.x] += s[threadIdx.x + o];
        __syncthreads();
    }
    if (threadIdx.x == 0) atomicAdd(&g_mindsum, s[0]);
}

__global__ void vq_gather(const float* __restrict__ lat, const float* __restrict__ emb,
                          float* __restrict__ outq)
{
    __shared__ float s[256];
    int i4 = blockIdx.x * blockDim.x + threadIdx.x;
    float ls = 0.f;
    if (i4 < BN * DN / 4) {
        int b   = i4 >> 6;
        int idx = g_minidx[b];
        float4 l = reinterpret_cast<const float4*>(lat)[i4];
        float4 q = reinterpret_cast<const float4*>(emb)[(size_t)idx * (DN / 4) + (i4 & 63)];
        float4 o; float d;
        d = __fsub_rn(q.x, l.x); o.x = __fadd_rn(l.x, d); ls = __fmaf_rn(d, d, ls);
        d = __fsub_rn(q.y, l.y); o.y = __fadd_rn(l.y, d); ls = __fmaf_rn(d, d, ls);
        d = __fsub_rn(q.z, l.z); o.z = __fadd_rn(l.z, d); ls = __fmaf_rn(d, d, ls);
        d = __fsub_rn(q.w, l.w); o.w = __fadd_rn(l.w, d); ls = __fmaf_rn(d, d, ls);
        reinterpret_cast<float4*>(outq)[i4] = o;
    }
    s[threadIdx.x] = ls;
    __syncthreads();
    for (int o2 = 128; o2 > 0; o2 >>= 1) {
        if (threadIdx.x < o2) s[threadIdx.x] += s[threadIdx.x + o2];
        __syncthreads();
    }
    if (threadIdx.x == 0) atomicAdd(&g_sqsum, s[0]);
}

__global__ void vq_finalize(float* __restrict__ out_tail)
{
    __shared__ float s[256];
    float loc = 0.f;
    for (int k = threadIdx.x; k < KN; k += 256) {
        float p = (float)g_counts[k] * (1.0f / BN);
        loc += p * logf(p + 1e-10f);
    }
    s[threadIdx.x] = loc;
    __syncthreads();
    for (int o = 128; o > 0; o >>= 1) {
        if (threadIdx.x < o) s[threadIdx.x] += s[threadIdx.x + o];
        __syncthreads();
    }
    if (threadIdx.x == 0) {
        float mse = g_sqsum * (1.0f / (float)(BN * (size_t)DN));
        out_tail[0] = __fadd_rn(__fmul_rn(mse, 0.25f), mse);
        out_tail[1] = -s[0];
        out_tail[2 + BN] = g_mindsum * (1.0f / BN);
    }
}

// ---------------------------------------------------------------------------
extern "C" void kernel_launch(void* const* d_in, const int* in_sizes, int n_in,
                              void* d_out, int out_size)
{
    (void)in_sizes; (void)n_in; (void)out_size;
    const float* lat = (const float*)d_in[0];   // [BN, DN] fp32
    const float* emb = (const float*)d_in[1];   // [KN, DN] fp32
    float* out = (float*)d_out;

    cudaFuncSetAttribute(vq_gemm,
                         cudaFuncAttributeMaxDynamicSharedMemorySize, SMEM_TOT);

    vq_init<<<(KN + 255) / 256, 256>>>();
    vq_rowsumsq<<<(BN * 32) / 256, 256>>>(lat, BN, 0);
    vq_rowsumsq<<<(KN * 32) / 256, 256>>>(emb, KN, 1);
    vq_gemm<<<(BN / 128) * (KN / 128), 256, SMEM_TOT>>>();
    vq_select<<<BN / 8, 256>>>(lat, emb);
    vq_hist<<<BN / 256, 256>>>(out + IND_OFF);
    vq_gather<<<(BN * DN / 4) / 256, 256>>>(lat, emb, out + Q_OFF);
    vq_finalize<<<1, 256>>>(out + TAIL_OFF);
}